// round 3
// baseline (speedup 1.0000x reference)
#include <cuda_runtime.h>
#include <cuda_bf16.h>

// PINN forward-mode dual-number evaluation:
// streams: v (value), vz (d/dz), vt (d/dt), vzz (d2/dz2)
// Linear: all streams multiply by W. tanh chain:
//   h = tanh(u); d = 1-h^2; hz = d*uz; ht = d*ut; hzz = d*uzz - 2*h*uz*hz

#define D1 128
#define D2 128
#define D3 64
#define NPTS 32
#define THREADS 256

// Shared layout (floats):
//   sW2 : [0, 16384)            128x128
//   sW3 : [16384, 24576)        128x64
//   sB2 : [24576, 24704)
//   sB3 : [24704, 24768)
//   sW4 : [24768, 24832)
//   sB4 : [24832, 24836)
//   A   : float offset 24836 (byte 99344, 16B aligned), 128*32 float4 (64KB)
//   B   : float offset 41220 (byte 164880, 16B aligned), 128*32 float4 (64KB)
// total = 230416 bytes (<= 232448 opt-in max)
#define SMEM_BYTES 230416
#define OFF_W3 16384
#define OFF_B2 24576
#define OFF_B3 24704
#define OFF_W4 24768
#define OFF_B4 24832
#define OFF_A  24836
#define OFF_B  (24836 + 16384)

__global__ __launch_bounds__(THREADS, 1)
void pinn_kernel(const float* __restrict__ x,
                 const float* __restrict__ W1, const float* __restrict__ b1,
                 const float* __restrict__ W2, const float* __restrict__ b2,
                 const float* __restrict__ W3, const float* __restrict__ b3,
                 const float* __restrict__ W4, const float* __restrict__ b4,
                 float* __restrict__ out, int n, int ntiles)
{
    extern __shared__ float smem[];
    float* sW2 = smem;
    float* sW3 = smem + OFF_W3;
    float* sB2 = smem + OFF_B2;
    float* sB3 = smem + OFF_B3;
    float* sW4 = smem + OFF_W4;
    float* sB4 = smem + OFF_B4;
    float4* A  = reinterpret_cast<float4*>(smem + OFF_A);
    float4* B  = reinterpret_cast<float4*>(smem + OFF_B);

    const int tid  = threadIdx.x;
    const int warp = tid >> 5;
    const int lane = tid & 31;

    // Stage weights into shared (once per block; block is persistent)
    for (int i = tid; i < D1 * D2; i += THREADS) sW2[i] = W2[i];
    for (int i = tid; i < D2 * D3; i += THREADS) sW3[i] = W3[i];
    if (tid < D2) sB2[tid] = b2[tid];
    if (tid < D3) sB3[tid] = b3[tid];
    if (tid < D3) sW4[tid] = W4[tid];
    if (tid == 0) sB4[0] = b4[0];
    __syncthreads();

    for (int tile = blockIdx.x; tile < ntiles; tile += gridDim.x) {
        const int p0 = tile * NPTS;
        int p = p0 + lane;
        if (p >= n) p = n - 1;   // clamp (N divisible by 32; safety only)

        // ---------------- Layer 1: 3 -> 128 ----------------
        // warp g computes neurons j = g*16 .. g*16+15, point = lane
        {
            const float xz = __ldg(&x[p * 3 + 0]);
            const float xt = __ldg(&x[p * 3 + 1]);
            const float xh = __ldg(&x[p * 3 + 2]);
            const int jb = warp * 16;
            #pragma unroll
            for (int jj = 0; jj < 16; ++jj) {
                const int j = jb + jj;
                const float w0 = __ldg(&W1[j]);          // row 0 (z)
                const float w1 = __ldg(&W1[D1 + j]);     // row 1 (t)
                const float w2 = __ldg(&W1[2 * D1 + j]); // row 2 (theta)
                float u  = fmaf(w0, xz, fmaf(w1, xt, fmaf(w2, xh, __ldg(&b1[j]))));
                float uz = w0;
                float ut = w1;
                // uzz = 0
                float h  = tanhf(u);
                float d  = fmaf(-h, h, 1.0f);
                float hz = d * uz;
                float ht = d * ut;
                float hzz = -2.0f * h * uz * hz;
                A[j * NPTS + lane] = make_float4(h, hz, ht, hzz);
            }
        }
        __syncthreads();

        // ---------------- Layer 2: 128 -> 128 ----------------
        // warp g computes neurons j = g*16 .. +15 for all 32 points (point = lane)
        {
            float av[16], az[16], at_[16], azz[16];
            #pragma unroll
            for (int q = 0; q < 16; ++q) { av[q] = 0.f; az[q] = 0.f; at_[q] = 0.f; azz[q] = 0.f; }

            const int jb = warp * 16;
            #pragma unroll 2
            for (int i = 0; i < D1; ++i) {
                const float4 h = A[i * NPTS + lane];
                const float4* wr = reinterpret_cast<const float4*>(sW2 + i * D2 + jb);
                #pragma unroll
                for (int q = 0; q < 4; ++q) {
                    const float4 w = wr[q];
                    const int j = q * 4;
                    av [j+0] = fmaf(w.x, h.x, av [j+0]);
                    az [j+0] = fmaf(w.x, h.y, az [j+0]);
                    at_[j+0] = fmaf(w.x, h.z, at_[j+0]);
                    azz[j+0] = fmaf(w.x, h.w, azz[j+0]);
                    av [j+1] = fmaf(w.y, h.x, av [j+1]);
                    az [j+1] = fmaf(w.y, h.y, az [j+1]);
                    at_[j+1] = fmaf(w.y, h.z, at_[j+1]);
                    azz[j+1] = fmaf(w.y, h.w, azz[j+1]);
                    av [j+2] = fmaf(w.z, h.x, av [j+2]);
                    az [j+2] = fmaf(w.z, h.y, az [j+2]);
                    at_[j+2] = fmaf(w.z, h.z, at_[j+2]);
                    azz[j+2] = fmaf(w.z, h.w, azz[j+2]);
                    av [j+3] = fmaf(w.w, h.x, av [j+3]);
                    az [j+3] = fmaf(w.w, h.y, az [j+3]);
                    at_[j+3] = fmaf(w.w, h.z, at_[j+3]);
                    azz[j+3] = fmaf(w.w, h.w, azz[j+3]);
                }
            }
            __syncthreads();  // all warps done reading A before anyone writes B? (B distinct; sync also orders B for L3)
            #pragma unroll
            for (int jj = 0; jj < 16; ++jj) {
                const int j = jb + jj;
                float u   = av[jj] + sB2[j];
                float uz  = az[jj];
                float ut  = at_[jj];
                float uzz = azz[jj];
                float h  = tanhf(u);
                float d  = fmaf(-h, h, 1.0f);
                float hz = d * uz;
                float ht = d * ut;
                float hzz = fmaf(d, uzz, -2.0f * h * uz * hz);
                B[j * NPTS + lane] = make_float4(h, hz, ht, hzz);
            }
        }
        __syncthreads();

        // ---------------- Layer 3: 128 -> 64 ----------------
        // warp g computes neurons j = g*8 .. +7
        {
            float av[8], az[8], at_[8], azz[8];
            #pragma unroll
            for (int q = 0; q < 8; ++q) { av[q] = 0.f; az[q] = 0.f; at_[q] = 0.f; azz[q] = 0.f; }

            const int jb = warp * 8;
            #pragma unroll 2
            for (int i = 0; i < D2; ++i) {
                const float4 h = B[i * NPTS + lane];
                const float4* wr = reinterpret_cast<const float4*>(sW3 + i * D3 + jb);
                #pragma unroll
                for (int q = 0; q < 2; ++q) {
                    const float4 w = wr[q];
                    const int j = q * 4;
                    av [j+0] = fmaf(w.x, h.x, av [j+0]);
                    az [j+0] = fmaf(w.x, h.y, az [j+0]);
                    at_[j+0] = fmaf(w.x, h.z, at_[j+0]);
                    azz[j+0] = fmaf(w.x, h.w, azz[j+0]);
                    av [j+1] = fmaf(w.y, h.x, av [j+1]);
                    az [j+1] = fmaf(w.y, h.y, az [j+1]);
                    at_[j+1] = fmaf(w.y, h.z, at_[j+1]);
                    azz[j+1] = fmaf(w.y, h.w, azz[j+1]);
                    av [j+2] = fmaf(w.z, h.x, av [j+2]);
                    az [j+2] = fmaf(w.z, h.y, az [j+2]);
                    at_[j+2] = fmaf(w.z, h.z, at_[j+2]);
                    azz[j+2] = fmaf(w.z, h.w, azz[j+2]);
                    av [j+3] = fmaf(w.w, h.x, av [j+3]);
                    az [j+3] = fmaf(w.w, h.y, az [j+3]);
                    at_[j+3] = fmaf(w.w, h.z, at_[j+3]);
                    azz[j+3] = fmaf(w.w, h.w, azz[j+3]);
                }
            }
            __syncthreads();  // all warps done reading B before A is overwritten below
            #pragma unroll
            for (int jj = 0; jj < 8; ++jj) {
                const int j = jb + jj;
                float u   = av[jj] + sB3[j];
                float uz  = az[jj];
                float ut  = at_[jj];
                float uzz = azz[jj];
                float h  = tanhf(u);
                float d  = fmaf(-h, h, 1.0f);
                float hz = d * uz;
                float ht = d * ut;
                float hzz = fmaf(d, uzz, -2.0f * h * uz * hz);
                A[j * NPTS + lane] = make_float4(h, hz, ht, hzz);
            }
        }
        __syncthreads();

        // ---------------- Layer 4: 64 -> 1 (warp 0 only; trivial cost) ----------------
        if (warp == 0) {
            float rv = sB4[0], rz = 0.f, rt = 0.f, rzz = 0.f;
            #pragma unroll 4
            for (int i = 0; i < D3; ++i) {
                const float4 h = A[i * NPTS + lane];
                const float w = sW4[i];
                rv  = fmaf(w, h.x, rv);
                rz  = fmaf(w, h.y, rz);
                rt  = fmaf(w, h.z, rt);
                rzz = fmaf(w, h.w, rzz);
            }
            const int pp = p0 + lane;
            if (pp < n) {
                reinterpret_cast<float4*>(out)[pp] = make_float4(rv, rz, rt, rzz);
            }
        }
        __syncthreads();  // protect A/B for next tile iteration
    }
}

extern "C" void kernel_launch(void* const* d_in, const int* in_sizes, int n_in,
                              void* d_out, int out_size)
{
    const float* x  = (const float*)d_in[0];
    const float* W1 = (const float*)d_in[1];
    const float* b1 = (const float*)d_in[2];
    const float* W2 = (const float*)d_in[3];
    const float* b2 = (const float*)d_in[4];
    const float* W3 = (const float*)d_in[5];
    const float* b3 = (const float*)d_in[6];
    const float* W4 = (const float*)d_in[7];
    const float* b4 = (const float*)d_in[8];
    float* out = (float*)d_out;

    const int n = in_sizes[0] / 3;
    const int ntiles = (n + NPTS - 1) / NPTS;

    int sms = 148;
    (void)cudaDeviceGetAttribute(&sms, cudaDevAttrMultiProcessorCount, 0);

    (void)cudaFuncSetAttribute(pinn_kernel,
                               cudaFuncAttributeMaxDynamicSharedMemorySize, SMEM_BYTES);

    int grid = sms;
    if (grid > ntiles) grid = ntiles;
    pinn_kernel<<<grid, THREADS, SMEM_BYTES>>>(x, W1, b1, W2, b2, W3, b3, W4, b4,
                                               out, n, ntiles);
}

// round 5
// speedup vs baseline: 1.1565x; 1.1565x over previous
#include <cuda_runtime.h>
#include <cuda_bf16.h>

// PINN forward-mode dual evaluation, 4 streams: v, vz, vt, vzz.
//   h = tanh(u); d = 1-h^2; hz = d*uz; ht = d*ut; hzz = d*uzz - 2*h*uz*hz
// Round-4 changes: fma.rn.f32x2 packed accumulation (neuron pairs),
// 512 threads (16 warps), tanh.approx.f32.

#define D1 128
#define D2 128
#define D3 64
#define NPTS 32
#define THREADS 512

// Shared layout (floats):
//   sW2 : [0, 16384)            128x128
//   sW3 : [16384, 24576)        128x64
//   sB2 : [24576, 24704)
//   sB3 : [24704, 24768)
//   sW4 : [24768, 24832)
//   sB4 : [24832, 24836)
//   A   : float offset 24836 (byte 99344, 16B aligned), 128*32 float4 (64KB)
//   B   : float offset 41220 (byte 164880, 16B aligned), 128*32 float4 (64KB)
// total = 230416 bytes (<= 232448 opt-in max)
#define SMEM_BYTES 230416
#define OFF_W3 16384
#define OFF_B2 24576
#define OFF_B3 24704
#define OFF_W4 24768
#define OFF_B4 24832
#define OFF_A  24836
#define OFF_B  (24836 + 16384)

__device__ __forceinline__ float tanh_fast(float x) {
    float y;
    asm("tanh.approx.f32 %0, %1;" : "=f"(y) : "f"(x));
    return y;
}

// duplicate one float into both halves of a 64-bit f32x2 register
__device__ __forceinline__ unsigned long long dup2(float v) {
    unsigned long long r;
    unsigned u = __float_as_uint(v);
    asm("mov.b64 %0, {%1, %2};" : "=l"(r) : "r"(u), "r"(u));
    return r;
}

// d = a * b + d   elementwise on packed f32x2 (Blackwell FFMA2)
__device__ __forceinline__ void fma2(unsigned long long& d,
                                     unsigned long long a,
                                     unsigned long long b) {
    asm("fma.rn.f32x2 %0, %1, %2, %0;" : "+l"(d) : "l"(a), "l"(b));
}

__device__ __forceinline__ float2 unpack2(unsigned long long v) {
    float2 r;
    asm("mov.b64 {%0, %1}, %2;" : "=f"(r.x), "=f"(r.y) : "l"(v));
    return r;
}

__global__ __launch_bounds__(THREADS, 1)
void pinn_kernel(const float* __restrict__ x,
                 const float* __restrict__ W1, const float* __restrict__ b1,
                 const float* __restrict__ W2, const float* __restrict__ b2,
                 const float* __restrict__ W3, const float* __restrict__ b3,
                 const float* __restrict__ W4, const float* __restrict__ b4,
                 float* __restrict__ out, int n, int ntiles)
{
    extern __shared__ float smem[];
    float* sW2 = smem;
    float* sW3 = smem + OFF_W3;
    float* sB2 = smem + OFF_B2;
    float* sB3 = smem + OFF_B3;
    float* sW4 = smem + OFF_W4;
    float* sB4 = smem + OFF_B4;
    float4* A  = reinterpret_cast<float4*>(smem + OFF_A);
    float4* B  = reinterpret_cast<float4*>(smem + OFF_B);

    const int tid  = threadIdx.x;
    const int warp = tid >> 5;     // 0..15
    const int lane = tid & 31;

    // Stage weights into shared once (block is persistent)
    for (int i = tid; i < D1 * D2; i += THREADS) sW2[i] = W2[i];
    for (int i = tid; i < D2 * D3; i += THREADS) sW3[i] = W3[i];
    if (tid < D2) sB2[tid] = b2[tid];
    if (tid < D3) sB3[tid] = b3[tid];
    if (tid < D3) sW4[tid] = W4[tid];
    if (tid == 0) sB4[0] = b4[0];
    __syncthreads();

    for (int tile = blockIdx.x; tile < ntiles; tile += gridDim.x) {
        const int p0 = tile * NPTS;
        int p = p0 + lane;
        if (p >= n) p = n - 1;   // safety clamp (N divisible by 32)

        // ---------------- Layer 1: 3 -> 128 (warp w: neurons w*8..w*8+7) ----
        {
            const float xz = __ldg(&x[p * 3 + 0]);
            const float xt = __ldg(&x[p * 3 + 1]);
            const float xh = __ldg(&x[p * 3 + 2]);
            const int jb = warp * 8;
            #pragma unroll
            for (int jj = 0; jj < 8; ++jj) {
                const int j = jb + jj;
                const float w0 = __ldg(&W1[j]);
                const float w1 = __ldg(&W1[D1 + j]);
                const float w2 = __ldg(&W1[2 * D1 + j]);
                float u  = fmaf(w0, xz, fmaf(w1, xt, fmaf(w2, xh, __ldg(&b1[j]))));
                float h  = tanh_fast(u);
                float d  = fmaf(-h, h, 1.0f);
                float hz = d * w0;         // uz = w0
                float ht = d * w1;         // ut = w1
                float hzz = -2.0f * h * w0 * hz;   // uzz = 0
                A[j * NPTS + lane] = make_float4(h, hz, ht, hzz);
            }
        }
        __syncthreads();   // S1: A complete

        // ---------------- Layer 2: 128 -> 128 (warp w: neurons w*8..+7) ----
        {
            unsigned long long acc[4][4];   // [neuron pair][stream]
            #pragma unroll
            for (int pq = 0; pq < 4; ++pq)
                #pragma unroll
                for (int s = 0; s < 4; ++s) acc[pq][s] = 0ULL;

            const int jb = warp * 8;
            #pragma unroll 4
            for (int i = 0; i < D1; ++i) {
                const float4 h = A[i * NPTS + lane];
                const unsigned long long d0 = dup2(h.x);
                const unsigned long long d1 = dup2(h.y);
                const unsigned long long d2 = dup2(h.z);
                const unsigned long long d3 = dup2(h.w);
                const ulonglong2* wr =
                    reinterpret_cast<const ulonglong2*>(sW2 + i * D2 + jb);
                const ulonglong2 wA = wr[0];  // pairs (w0,w1),(w2,w3)
                const ulonglong2 wB = wr[1];  // pairs (w4,w5),(w6,w7)
                fma2(acc[0][0], wA.x, d0); fma2(acc[0][1], wA.x, d1);
                fma2(acc[0][2], wA.x, d2); fma2(acc[0][3], wA.x, d3);
                fma2(acc[1][0], wA.y, d0); fma2(acc[1][1], wA.y, d1);
                fma2(acc[1][2], wA.y, d2); fma2(acc[1][3], wA.y, d3);
                fma2(acc[2][0], wB.x, d0); fma2(acc[2][1], wB.x, d1);
                fma2(acc[2][2], wB.x, d2); fma2(acc[2][3], wB.x, d3);
                fma2(acc[3][0], wB.y, d0); fma2(acc[3][1], wB.y, d1);
                fma2(acc[3][2], wB.y, d2); fma2(acc[3][3], wB.y, d3);
            }
            #pragma unroll
            for (int pq = 0; pq < 4; ++pq) {
                const float2 fv  = unpack2(acc[pq][0]);
                const float2 fz  = unpack2(acc[pq][1]);
                const float2 ft  = unpack2(acc[pq][2]);
                const float2 fzz = unpack2(acc[pq][3]);
                #pragma unroll
                for (int half = 0; half < 2; ++half) {
                    const int j = jb + pq * 2 + half;
                    const float u   = (half ? fv.y  : fv.x)  + sB2[j];
                    const float uz  = (half ? fz.y  : fz.x);
                    const float ut  = (half ? ft.y  : ft.x);
                    const float uzz = (half ? fzz.y : fzz.x);
                    const float h  = tanh_fast(u);
                    const float d  = fmaf(-h, h, 1.0f);
                    const float hz = d * uz;
                    const float ht = d * ut;
                    const float hzz = fmaf(d, uzz, -2.0f * h * uz * hz);
                    B[j * NPTS + lane] = make_float4(h, hz, ht, hzz);
                }
            }
        }
        __syncthreads();   // S2: all layer-2 A-reads done, B complete

        // ---------------- Layer 3: 128 -> 64 (warp w: neurons w*4..+3) -----
        {
            unsigned long long acc[2][4];
            #pragma unroll
            for (int pq = 0; pq < 2; ++pq)
                #pragma unroll
                for (int s = 0; s < 4; ++s) acc[pq][s] = 0ULL;

            const int jb = warp * 4;
            #pragma unroll 4
            for (int i = 0; i < D2; ++i) {
                const float4 h = B[i * NPTS + lane];
                const unsigned long long d0 = dup2(h.x);
                const unsigned long long d1 = dup2(h.y);
                const unsigned long long d2 = dup2(h.z);
                const unsigned long long d3 = dup2(h.w);
                const ulonglong2 wA =
                    *reinterpret_cast<const ulonglong2*>(sW3 + i * D3 + jb);
                fma2(acc[0][0], wA.x, d0); fma2(acc[0][1], wA.x, d1);
                fma2(acc[0][2], wA.x, d2); fma2(acc[0][3], wA.x, d3);
                fma2(acc[1][0], wA.y, d0); fma2(acc[1][1], wA.y, d1);
                fma2(acc[1][2], wA.y, d2); fma2(acc[1][3], wA.y, d3);
            }
            #pragma unroll
            for (int pq = 0; pq < 2; ++pq) {
                const float2 fv  = unpack2(acc[pq][0]);
                const float2 fz  = unpack2(acc[pq][1]);
                const float2 ft  = unpack2(acc[pq][2]);
                const float2 fzz = unpack2(acc[pq][3]);
                #pragma unroll
                for (int half = 0; half < 2; ++half) {
                    const int j = jb + pq * 2 + half;
                    const float u   = (half ? fv.y  : fv.x)  + sB3[j];
                    const float uz  = (half ? fz.y  : fz.x);
                    const float ut  = (half ? ft.y  : ft.x);
                    const float uzz = (half ? fzz.y : fzz.x);
                    const float h  = tanh_fast(u);
                    const float d  = fmaf(-h, h, 1.0f);
                    const float hz = d * uz;
                    const float ht = d * ut;
                    const float hzz = fmaf(d, uzz, -2.0f * h * uz * hz);
                    A[j * NPTS + lane] = make_float4(h, hz, ht, hzz);
                }
            }
        }
        __syncthreads();   // S3: all layer-3 B-reads done, A (64 rows) complete

        // ---------------- Layer 4: 64 -> 1 (warps 0-3, one stream each) ----
        if (warp < 4) {
            const int s = warp;            // stream index
            float acc = (s == 0) ? sB4[0] : 0.0f;
            const float* Af = smem + OFF_A;
            #pragma unroll 8
            for (int i = 0; i < D3; ++i) {
                const float hv = Af[(i * NPTS + lane) * 4 + s];
                acc = fmaf(sW4[i], hv, acc);
            }
            const int pp = p0 + lane;
            if (pp < n) out[pp * 4 + s] = acc;
        }
        __syncthreads();   // S4: layer-4 A-reads done before next tile
    }
}

extern "C" void kernel_launch(void* const* d_in, const int* in_sizes, int n_in,
                              void* d_out, int out_size)
{
    const float* x  = (const float*)d_in[0];
    const float* W1 = (const float*)d_in[1];
    const float* b1 = (const float*)d_in[2];
    const float* W2 = (const float*)d_in[3];
    const float* b2 = (const float*)d_in[4];
    const float* W3 = (const float*)d_in[5];
    const float* b3 = (const float*)d_in[6];
    const float* W4 = (const float*)d_in[7];
    const float* b4 = (const float*)d_in[8];
    float* out = (float*)d_out;

    const int n = in_sizes[0] / 3;
    const int ntiles = (n + NPTS - 1) / NPTS;

    int sms = 148;
    (void)cudaDeviceGetAttribute(&sms, cudaDevAttrMultiProcessorCount, 0);

    (void)cudaFuncSetAttribute(pinn_kernel,
                               cudaFuncAttributeMaxDynamicSharedMemorySize, SMEM_BYTES);

    int grid = sms;
    if (grid > ntiles) grid = ntiles;
    pinn_kernel<<<grid, THREADS, SMEM_BYTES>>>(x, W1, b1, W2, b2, W3, b3, W4, b4,
                                               out, n, ntiles);
}